// round 4
// baseline (speedup 1.0000x reference)
#include <cuda_runtime.h>
#include <cstdint>

// Problem dims
constexpr int kT  = 8192;
constexpr int kNS = 512;
constexpr int kNH = 1024;
constexpr int kNO = 512;
constexpr int kNG = 4 * kNH;  // 4096 gate rows

constexpr int kNumCTA = 128;        // persistent CTAs (1/SM, < 148 SMs -> co-resident)
constexpr int kUnitsPerCTA = kNH / kNumCTA;  // 8 hidden units per CTA

// ---------------- scratch (static device allocations; no cudaMalloc) ----------------
__device__ float g_Z[(size_t)kT * kNG];    // 128 MB: gate preactivations / reused for logits
__device__ float g_H0[(size_t)kT * kNH];   // 32 MB
__device__ float g_H1[(size_t)kT * kNH];   // 32 MB
__device__ int   g_cnt[2 * kT];            // per-step arrive counters (phase A, phase B)

// ---------------- init ----------------
__global__ void zero_cnt_kernel(int* c, int n) {
    int i = blockIdx.x * blockDim.x + threadIdx.x;
    if (i < n) c[i] = 0;
}

// ---------------- fp32 tiled GEMM: C[M,N] = A[M,K] * B[N,K]^T (+bias1[n]+bias2[n]) ----
// A, B row-major with contiguous K. 128x128 block, BK=8, 256 threads, 8x8 per thread.
__global__ __launch_bounds__(256) void gemm_nt(
    const float* __restrict__ A, const float* __restrict__ B,
    const float* __restrict__ b1, const float* __restrict__ b2,
    float* __restrict__ C, int M, int N, int K)
{
    __shared__ float As[8][128];
    __shared__ float Bs[8][128];
    const int tid = threadIdx.x;
    const int m0 = blockIdx.y * 128;
    const int n0 = blockIdx.x * 128;
    const int ty = tid >> 4;          // 0..15
    const int tx = tid & 15;          // 0..15
    const int lrow = tid >> 1;        // 0..127
    const int lk = (tid & 1) * 4;     // 0 or 4
    const float* Ap = A + (size_t)(m0 + lrow) * K + lk;
    const float* Bp = B + (size_t)(n0 + lrow) * K + lk;

    float acc[8][8];
#pragma unroll
    for (int i = 0; i < 8; i++)
#pragma unroll
        for (int j = 0; j < 8; j++) acc[i][j] = 0.f;

    for (int k0 = 0; k0 < K; k0 += 8) {
        float4 av = *(const float4*)(Ap + k0);
        float4 bv = *(const float4*)(Bp + k0);
        As[lk + 0][lrow] = av.x; As[lk + 1][lrow] = av.y;
        As[lk + 2][lrow] = av.z; As[lk + 3][lrow] = av.w;
        Bs[lk + 0][lrow] = bv.x; Bs[lk + 1][lrow] = bv.y;
        Bs[lk + 2][lrow] = bv.z; Bs[lk + 3][lrow] = bv.w;
        __syncthreads();
#pragma unroll
        for (int kk = 0; kk < 8; kk++) {
            float a[8], b[8];
#pragma unroll
            for (int i = 0; i < 8; i++) a[i] = As[kk][i * 16 + ty];
#pragma unroll
            for (int j = 0; j < 8; j++) b[j] = Bs[kk][j * 16 + tx];
#pragma unroll
            for (int i = 0; i < 8; i++)
#pragma unroll
                for (int j = 0; j < 8; j++) acc[i][j] += a[i] * b[j];
        }
        __syncthreads();
    }

#pragma unroll
    for (int j = 0; j < 8; j++) {
        int n = n0 + j * 16 + tx;
        float bias = 0.f;
        if (b1) bias += b1[n];
        if (b2) bias += b2[n];
#pragma unroll
        for (int i = 0; i < 8; i++) {
            int m = m0 + i * 16 + ty;
            C[(size_t)m * N + n] = acc[i][j] + bias;
        }
    }
}

// ---------------- persistent LSTM recurrence ----------------
// Z: [T, 4096] precomputed x-projection WITH biases already added.
// Whh: [4096, 1024] row-major (torch gate order i,f,g,o).
// H:  [T, 1024] output hidden states.
// cnt: per-step arrive counters (zeroed before launch).
// Each CTA b owns hidden units b*8 .. b*8+7 (32 gate rows) held in SMEM.
__global__ __launch_bounds__(256) void lstm_rec(
    const float* __restrict__ Z, const float* __restrict__ Whh,
    float* H, int* cnt)
{
    extern __shared__ float sm[];
    float* sW   = sm;                 // 32 * 1024 weights
    float* sDot = sm + 32 * 1024;     // 32 gate dot products
    float* sC   = sDot + 32;          // 8 cell states

    const int tid  = threadIdx.x;
    const int b    = blockIdx.x;
    const int warp = tid >> 5;
    const int lane = tid & 31;

    // Load this CTA's 32 weight rows into SMEM (gate-major: lr = g*8+u)
    for (int i = tid; i < 32 * 1024; i += 256) {
        int lr = i >> 10, k = i & 1023;
        int g = lr >> 3, u = lr & 7;
        sW[i] = Whh[(size_t)(g * kNH + b * kUnitsPerCTA + u) * kNH + k];
    }
    if (tid < kUnitsPerCTA) sC[tid] = 0.f;
    __syncthreads();

    float hreg[32];
    for (int t = 0; t < kT; t++) {
        // ---- acquire h[t-1] ----
        if (t == 0) {
#pragma unroll
            for (int j = 0; j < 32; j++) hreg[j] = 0.f;
        } else {
            if (tid == 0) {
                volatile int* p = cnt + (t - 1);
                while (*p < kNumCTA) { }
                __threadfence();
            }
            __syncthreads();
            const float* hp = H + (size_t)(t - 1) * kNH;
#pragma unroll
            for (int j = 0; j < 32; j++) hreg[j] = hp[j * 32 + lane];
        }

        // ---- matvec: each warp computes 4 gate rows ----
#pragma unroll
        for (int r = 0; r < 4; r++) {
            int lr = warp * 4 + r;
            const float* wr = sW + lr * kNH;
            float s = 0.f;
#pragma unroll
            for (int j = 0; j < 32; j++) s += wr[j * 32 + lane] * hreg[j];
#pragma unroll
            for (int off = 16; off; off >>= 1)
                s += __shfl_xor_sync(0xffffffffu, s, off);
            if (lane == 0) sDot[lr] = s;
        }
        __syncthreads();

        // ---- activations + state update (8 threads, warp 0) ----
        if (tid < kUnitsPerCTA) {
            int u = tid;
            const float* zrow = Z + (size_t)t * kNG;
            int col = b * kUnitsPerCTA + u;
            float zi = sDot[u]      + zrow[col];
            float zf = sDot[8 + u]  + zrow[kNH + col];
            float zg = sDot[16 + u] + zrow[2 * kNH + col];
            float zo = sDot[24 + u] + zrow[3 * kNH + col];
            float ig = 1.f / (1.f + expf(-zi));
            float fg = 1.f / (1.f + expf(-zf));
            float gg = tanhf(zg);
            float og = 1.f / (1.f + expf(-zo));
            float c = fg * sC[u] + ig * gg;
            sC[u] = c;
            H[(size_t)t * kNH + col] = og * tanhf(c);
        }
        // release: STG (lanes 0..7) -> MEMBAR.GPU -> ATOMG, all in warp 0's stream
        if (warp == 0) {
            __syncwarp();
            if (lane == 0) {
                __threadfence();
                atomicAdd(cnt + t, 1);
            }
        }
        __syncthreads();  // protects sDot/hreg reuse next step
    }
}

// ---------------- softmax over NO=512 per row ----------------
__global__ __launch_bounds__(256) void softmax_rows(
    const float* __restrict__ L, float* __restrict__ out)
{
    __shared__ float red[256];
    int t = blockIdx.x, tid = threadIdx.x;
    const float* row = L + (size_t)t * kNO;
    float v0 = row[tid], v1 = row[tid + 256];
    float m = fmaxf(v0, v1);
    red[tid] = m; __syncthreads();
    for (int s = 128; s; s >>= 1) {
        if (tid < s) red[tid] = fmaxf(red[tid], red[tid + s]);
        __syncthreads();
    }
    m = red[0]; __syncthreads();
    float e0 = expf(v0 - m), e1 = expf(v1 - m);
    red[tid] = e0 + e1; __syncthreads();
    for (int s = 128; s; s >>= 1) {
        if (tid < s) red[tid] += red[tid + s];
        __syncthreads();
    }
    float inv = 1.f / red[0];
    out[(size_t)t * kNO + tid]       = e0 * inv;
    out[(size_t)t * kNO + tid + 256] = e1 * inv;
}

// ---------------- value head: out[t] = H1[t] . w_val + b_val ----------------
__global__ __launch_bounds__(256) void value_head(
    const float* __restrict__ H1, const float* __restrict__ wv,
    const float* __restrict__ bv, float* __restrict__ out)
{
    __shared__ float red[256];
    int t = blockIdx.x, tid = threadIdx.x;
    const float* h = H1 + (size_t)t * kNH;
    float s = 0.f;
    for (int k = tid; k < kNH; k += 256) s += h[k] * wv[k];
    red[tid] = s; __syncthreads();
    for (int r = 128; r; r >>= 1) {
        if (tid < r) red[tid] += red[tid + r];
        __syncthreads();
    }
    if (tid == 0) out[t] = red[0] + bv[0];
}

// ---------------- launch ----------------
extern "C" void kernel_launch(void* const* d_in, const int* in_sizes, int n_in,
                              void* d_out, int out_size)
{
    (void)in_sizes; (void)n_in; (void)out_size;
    const float* x     = (const float*)d_in[0];
    const float* w_ih0 = (const float*)d_in[1];
    const float* w_hh0 = (const float*)d_in[2];
    const float* b_ih0 = (const float*)d_in[3];
    const float* b_hh0 = (const float*)d_in[4];
    const float* w_ih1 = (const float*)d_in[5];
    const float* w_hh1 = (const float*)d_in[6];
    const float* b_ih1 = (const float*)d_in[7];
    const float* b_hh1 = (const float*)d_in[8];
    const float* w_pol = (const float*)d_in[9];
    const float* b_pol = (const float*)d_in[10];
    const float* w_val = (const float*)d_in[11];
    const float* b_val = (const float*)d_in[12];
    float* out = (float*)d_out;

    float *Z, *H0, *H1;
    int* cnt;
    cudaGetSymbolAddress((void**)&Z, g_Z);
    cudaGetSymbolAddress((void**)&H0, g_H0);
    cudaGetSymbolAddress((void**)&H1, g_H1);
    cudaGetSymbolAddress((void**)&cnt, g_cnt);

    const int smem = (32 * 1024 + 32 + 8) * (int)sizeof(float);
    cudaFuncSetAttribute(lstm_rec, cudaFuncAttributeMaxDynamicSharedMemorySize, smem);

    // reset per-step counters every launch (replay-deterministic)
    zero_cnt_kernel<<<(2 * kT + 255) / 256, 256>>>(cnt, 2 * kT);

    // Z0 = X @ w_ih0^T + (b_ih0 + b_hh0)
    gemm_nt<<<dim3(kNG / 128, kT / 128), 256>>>(x, w_ih0, b_ih0, b_hh0, Z, kT, kNG, kNS);
    // layer-0 recurrence -> H0
    lstm_rec<<<kNumCTA, 256, smem>>>(Z, w_hh0, H0, cnt);
    // Z1 = H0 @ w_ih1^T + (b_ih1 + b_hh1)
    gemm_nt<<<dim3(kNG / 128, kT / 128), 256>>>(H0, w_ih1, b_ih1, b_hh1, Z, kT, kNG, kNH);
    // layer-1 recurrence -> H1
    lstm_rec<<<kNumCTA, 256, smem>>>(Z, w_hh1, H1, cnt + kT);
    // policy logits = H1 @ w_pol^T + b_pol (into Z scratch)
    gemm_nt<<<dim3(kNO / 128, kT / 128), 256>>>(H1, w_pol, b_pol, nullptr, Z, kT, kNO, kNH);
    // softmax -> out[0 : T*NO)
    softmax_rows<<<kT, 256>>>(Z, out);
    // value -> out[T*NO : T*NO + T)
    value_head<<<kT, 256>>>(H1, w_val, b_val, out + (size_t)kT * kNO);
}

// round 5
// speedup vs baseline: 1.0344x; 1.0344x over previous
#include <cuda_runtime.h>
#include <cuda_fp16.h>
#include <cstdint>

// Problem dims
constexpr int kT  = 8192;
constexpr int kNS = 512;
constexpr int kNH = 1024;
constexpr int kNO = 512;
constexpr int kNG = 4 * kNH;  // 4096 gate rows

constexpr int kNumCTA = 128;                 // persistent CTAs (<148 SMs -> co-resident)
constexpr int kUnitsPerCTA = kNH / kNumCTA;  // 8 hidden units per CTA

// ---------------- scratch (static device allocations; no cudaMalloc) ----------------
__device__ float g_Z[(size_t)kT * kNG];    // 128 MB: gate preactivations / reused for logits
__device__ float g_H0[(size_t)kT * kNH];   // 32 MB
__device__ float g_H1[(size_t)kT * kNH];   // 32 MB
__device__ int   g_cnt[2 * kT];            // per-step arrive counters (phase A, phase B)

// ---------------- init ----------------
__global__ void zero_cnt_kernel(int* c, int n) {
    int i = blockIdx.x * blockDim.x + threadIdx.x;
    if (i < n) c[i] = 0;
}

// ---------------- fp32 tiled GEMM: C[M,N] = A[M,K] * B[N,K]^T (+bias1[n]+bias2[n]) ----
__global__ __launch_bounds__(256) void gemm_nt(
    const float* __restrict__ A, const float* __restrict__ B,
    const float* __restrict__ b1, const float* __restrict__ b2,
    float* __restrict__ C, int M, int N, int K)
{
    __shared__ float As[8][128];
    __shared__ float Bs[8][128];
    const int tid = threadIdx.x;
    const int m0 = blockIdx.y * 128;
    const int n0 = blockIdx.x * 128;
    const int ty = tid >> 4;          // 0..15
    const int tx = tid & 15;          // 0..15
    const int lrow = tid >> 1;        // 0..127
    const int lk = (tid & 1) * 4;     // 0 or 4
    const float* Ap = A + (size_t)(m0 + lrow) * K + lk;
    const float* Bp = B + (size_t)(n0 + lrow) * K + lk;

    float acc[8][8];
#pragma unroll
    for (int i = 0; i < 8; i++)
#pragma unroll
        for (int j = 0; j < 8; j++) acc[i][j] = 0.f;

    for (int k0 = 0; k0 < K; k0 += 8) {
        float4 av = *(const float4*)(Ap + k0);
        float4 bv = *(const float4*)(Bp + k0);
        As[lk + 0][lrow] = av.x; As[lk + 1][lrow] = av.y;
        As[lk + 2][lrow] = av.z; As[lk + 3][lrow] = av.w;
        Bs[lk + 0][lrow] = bv.x; Bs[lk + 1][lrow] = bv.y;
        Bs[lk + 2][lrow] = bv.z; Bs[lk + 3][lrow] = bv.w;
        __syncthreads();
#pragma unroll
        for (int kk = 0; kk < 8; kk++) {
            float a[8], b[8];
#pragma unroll
            for (int i = 0; i < 8; i++) a[i] = As[kk][i * 16 + ty];
#pragma unroll
            for (int j = 0; j < 8; j++) b[j] = Bs[kk][j * 16 + tx];
#pragma unroll
            for (int i = 0; i < 8; i++)
#pragma unroll
                for (int j = 0; j < 8; j++) acc[i][j] += a[i] * b[j];
        }
        __syncthreads();
    }

#pragma unroll
    for (int j = 0; j < 8; j++) {
        int n = n0 + j * 16 + tx;
        float bias = 0.f;
        if (b1) bias += b1[n];
        if (b2) bias += b2[n];
#pragma unroll
        for (int i = 0; i < 8; i++) {
            int m = m0 + i * 16 + ty;
            C[(size_t)m * N + n] = acc[i][j] + bias;
        }
    }
}

// ---------------- persistent LSTM recurrence (fp16 weights, fp32 accumulate) ------
// Z: [T, 4096] precomputed x-projection WITH biases already added.
// Whh: [4096, 1024] row-major fp32 (torch gate order i,f,g,o) -> converted to fp16 SMEM.
// H:  [T, 1024] output hidden states (fp32).
// cnt: per-step arrive counters (zeroed before launch).
// Each CTA b owns hidden units b*8 .. b*8+7 (32 gate rows) held in SMEM as half2.
__global__ __launch_bounds__(256) void lstm_rec(
    const float* __restrict__ Z, const float* __restrict__ Whh,
    float* H, int* cnt)
{
    extern __shared__ __half2 sW[];          // [32][512] half2 = 64 KB
    __shared__ float sDot[2][32];            // double-buffered gate dots

    const int tid  = threadIdx.x;
    const int b    = blockIdx.x;
    const int warp = tid >> 5;
    const int lane = tid & 31;

    // ---- load + convert this CTA's 32 weight rows (gate-major lr = g*8+u) ----
    for (int i = tid; i < 32 * 512; i += 256) {
        int lr = i >> 9, p = i & 511;
        int g = lr >> 3, u = lr & 7;
        const float2 wv = *(const float2*)(
            Whh + (size_t)(g * kNH + b * kUnitsPerCTA + u) * kNH + 2 * p);
        sW[i] = __floats2half2_rn(wv.x, wv.y);
    }
    __syncthreads();

    const __half2* wbase = sW + (size_t)(warp * 4) * 512;  // this warp's 4 rows
    float creg = 0.f;                                      // cell state (lanes 0..7 of warp 0)

    for (int t = 0; t < kT; t++) {
        // ---- prefetch Z[t] contribution (warp 0, lane = g*8+u) — off critical path
        float zv = 0.f;
        if (warp == 0) {
            zv = Z[(size_t)t * kNG + (lane >> 3) * kNH + b * kUnitsPerCTA + (lane & 7)];
        }

        // ---- acquire h[t-1] ----
        float2 h2[16];
        if (t == 0) {
#pragma unroll
            for (int j = 0; j < 16; j++) h2[j] = make_float2(0.f, 0.f);
        } else {
            const int* p = cnt + (t - 1);
            int v;
            do {
                asm volatile("ld.acquire.gpu.global.u32 %0, [%1];"
                             : "=r"(v) : "l"(p) : "memory");
            } while (v < kNumCTA);
            const float2* hp2 = (const float2*)(H + (size_t)(t - 1) * kNH);
#pragma unroll
            for (int j = 0; j < 16; j++) h2[j] = __ldcg(hp2 + j * 32 + lane);
        }

        // ---- matvec: each warp computes 4 gate rows, fp16 weights, fp32 acc ----
        float s0 = 0.f, s1 = 0.f, s2 = 0.f, s3 = 0.f;
#pragma unroll
        for (int j = 0; j < 16; j++) {
            const int idx = j * 32 + lane;
            float2 w0 = __half22float2(wbase[idx]);
            float2 w1 = __half22float2(wbase[512 + idx]);
            float2 w2 = __half22float2(wbase[1024 + idx]);
            float2 w3 = __half22float2(wbase[1536 + idx]);
            s0 = fmaf(w0.x, h2[j].x, fmaf(w0.y, h2[j].y, s0));
            s1 = fmaf(w1.x, h2[j].x, fmaf(w1.y, h2[j].y, s1));
            s2 = fmaf(w2.x, h2[j].x, fmaf(w2.y, h2[j].y, s2));
            s3 = fmaf(w3.x, h2[j].x, fmaf(w3.y, h2[j].y, s3));
        }
#pragma unroll
        for (int off = 16; off; off >>= 1) {
            s0 += __shfl_xor_sync(0xffffffffu, s0, off);
            s1 += __shfl_xor_sync(0xffffffffu, s1, off);
            s2 += __shfl_xor_sync(0xffffffffu, s2, off);
            s3 += __shfl_xor_sync(0xffffffffu, s3, off);
        }
        if (lane == 0) {
            float* d = &sDot[t & 1][warp * 4];
            d[0] = s0; d[1] = s1; d[2] = s2; d[3] = s3;
        }
        __syncthreads();  // sDot[t&1] complete

        // ---- activation + state update: warp 0 only; other warps proceed to poll t+1
        if (warp == 0) {
            float z = sDot[t & 1][lane] + zv;
            // uniform formula: sigmoid gates -> sig(z); g gate -> tanh(z)=2*sig(2z)-1
            const bool isg = (lane >= 16) & (lane < 24);
            const float sm = isg ? 2.f : 1.f;
            float sig = 1.f / (1.f + __expf(-sm * z));
            float a = isg ? fmaf(sig, 2.f, -1.f) : sig;
            const int u = lane & 7;
            float i_ = __shfl_sync(0xffffffffu, a, u);
            float f_ = __shfl_sync(0xffffffffu, a, 8 + u);
            float g_ = __shfl_sync(0xffffffffu, a, 16 + u);
            float o_ = __shfl_sync(0xffffffffu, a, 24 + u);
            if (lane < kUnitsPerCTA) {
                creg = fmaf(f_, creg, i_ * g_);
                float tc = 2.f / (1.f + __expf(-2.f * creg)) - 1.f;
                H[(size_t)t * kNH + b * kUnitsPerCTA + lane] = o_ * tc;
            }
            __syncwarp();
            if (lane == 0) {
                asm volatile("red.release.gpu.global.add.u32 [%0], %1;"
                             :: "l"(cnt + t), "r"(1) : "memory");
            }
        }
        // no trailing barrier: sDot is double-buffered, and no warp can pass the
        // poll for step t+1 until this CTA's warp 0 has released step t.
    }
}

// ---------------- softmax over NO=512 per row ----------------
__global__ __launch_bounds__(256) void softmax_rows(
    const float* __restrict__ L, float* __restrict__ out)
{
    __shared__ float red[256];
    int t = blockIdx.x, tid = threadIdx.x;
    const float* row = L + (size_t)t * kNO;
    float v0 = row[tid], v1 = row[tid + 256];
    float m = fmaxf(v0, v1);
    red[tid] = m; __syncthreads();
    for (int s = 128; s; s >>= 1) {
        if (tid < s) red[tid] = fmaxf(red[tid], red[tid + s]);
        __syncthreads();
    }
    m = red[0]; __syncthreads();
    float e0 = expf(v0 - m), e1 = expf(v1 - m);
    red[tid] = e0 + e1; __syncthreads();
    for (int s = 128; s; s >>= 1) {
        if (tid < s) red[tid] += red[tid + s];
        __syncthreads();
    }
    float inv = 1.f / red[0];
    out[(size_t)t * kNO + tid]       = e0 * inv;
    out[(size_t)t * kNO + tid + 256] = e1 * inv;
}

// ---------------- value head: out[t] = H1[t] . w_val + b_val ----------------
__global__ __launch_bounds__(256) void value_head(
    const float* __restrict__ H1, const float* __restrict__ wv,
    const float* __restrict__ bv, float* __restrict__ out)
{
    __shared__ float red[256];
    int t = blockIdx.x, tid = threadIdx.x;
    const float* h = H1 + (size_t)t * kNH;
    float s = 0.f;
    for (int k = tid; k < kNH; k += 256) s += h[k] * wv[k];
    red[tid] = s; __syncthreads();
    for (int r = 128; r; r >>= 1) {
        if (tid < r) red[tid] += red[tid + r];
        __syncthreads();
    }
    if (tid == 0) out[t] = red[0] + bv[0];
}

// ---------------- launch ----------------
extern "C" void kernel_launch(void* const* d_in, const int* in_sizes, int n_in,
                              void* d_out, int out_size)
{
    (void)in_sizes; (void)n_in; (void)out_size;
    const float* x     = (const float*)d_in[0];
    const float* w_ih0 = (const float*)d_in[1];
    const float* w_hh0 = (const float*)d_in[2];
    const float* b_ih0 = (const float*)d_in[3];
    const float* b_hh0 = (const float*)d_in[4];
    const float* w_ih1 = (const float*)d_in[5];
    const float* w_hh1 = (const float*)d_in[6];
    const float* b_ih1 = (const float*)d_in[7];
    const float* b_hh1 = (const float*)d_in[8];
    const float* w_pol = (const float*)d_in[9];
    const float* b_pol = (const float*)d_in[10];
    const float* w_val = (const float*)d_in[11];
    const float* b_val = (const float*)d_in[12];
    float* out = (float*)d_out;

    float *Z, *H0, *H1;
    int* cnt;
    cudaGetSymbolAddress((void**)&Z, g_Z);
    cudaGetSymbolAddress((void**)&H0, g_H0);
    cudaGetSymbolAddress((void**)&H1, g_H1);
    cudaGetSymbolAddress((void**)&cnt, g_cnt);

    const int smem = 32 * 512 * (int)sizeof(__half2);  // 64 KB
    cudaFuncSetAttribute(lstm_rec, cudaFuncAttributeMaxDynamicSharedMemorySize, smem);

    // reset per-step counters every launch (replay-deterministic)
    zero_cnt_kernel<<<(2 * kT + 255) / 256, 256>>>(cnt, 2 * kT);

    // Z0 = X @ w_ih0^T + (b_ih0 + b_hh0)
    gemm_nt<<<dim3(kNG / 128, kT / 128), 256>>>(x, w_ih0, b_ih0, b_hh0, Z, kT, kNG, kNS);
    // layer-0 recurrence -> H0
    lstm_rec<<<kNumCTA, 256, smem>>>(Z, w_hh0, H0, cnt);
    // Z1 = H0 @ w_ih1^T + (b_ih1 + b_hh1)
    gemm_nt<<<dim3(kNG / 128, kT / 128), 256>>>(H0, w_ih1, b_ih1, b_hh1, Z, kT, kNG, kNH);
    // layer-1 recurrence -> H1
    lstm_rec<<<kNumCTA, 256, smem>>>(Z, w_hh1, H1, cnt + kT);
    // policy logits = H1 @ w_pol^T + b_pol (into Z scratch)
    gemm_nt<<<dim3(kNO / 128, kT / 128), 256>>>(H1, w_pol, b_pol, nullptr, Z, kT, kNO, kNH);
    // softmax -> out[0 : T*NO)
    softmax_rows<<<kT, 256>>>(Z, out);
    // value -> out[T*NO : T*NO + T)
    value_head<<<kT, 256>>>(H1, w_val, b_val, out + (size_t)kT * kNO);
}